// round 12
// baseline (speedup 1.0000x reference)
#include <cuda_runtime.h>

#define VD 48
#define NC 16
#define G3 (VD*VD*VD)            // 110592 groups
#define DTOT (G3*VD)             // 5308416 cross-feature dims
#define D4 (DTOT/4)              // 1327104 float4 per class row
#define GX 162                   // blocks per class
#define TPB 256
#define STRIDE (GX*TPB)          // 41472 (divisible by 12)
#define ITERS (D4/STRIDE)        // 32
#define Q01N (VD*VD)             // 2304

__device__ float g_part[NC*GX];
__device__ unsigned int g_tick[NC];   // zero-init; reset by each class's last block

// acq_rel GPU-scope atomic add: orders this thread's prior global stores
// (release) without MEMBAR.GPU/CCTL.IVALL, and gives acquire for the reader.
__device__ __forceinline__ unsigned atom_add_acqrel(unsigned* p, unsigned v) {
    unsigned old;
    asm volatile("atom.acq_rel.gpu.global.add.u32 %0, [%1], %2;"
                 : "=r"(old) : "l"(p), "r"(v) : "memory");
    return old;
}

// Fused: streaming GEMV over W (340 MB, read once), p012 factored as
// q01[i0*48+i1] (shared) * x2[i2] (folded into x3 regs). Per-class fence-free
// ticket: last block of each class reduces that class's 162 partials (warp 0).
__global__ void __launch_bounds__(TPB) k_main(const float* __restrict__ W,
                                              const float* __restrict__ x,
                                              const float* __restrict__ b,
                                              float* __restrict__ out) {
    __shared__ float q01[Q01N];          // x0 (x) x1 outer product, 9 KB
    __shared__ float sred[TPB/32];

    // Build q01 cooperatively: 2304 / 256 = 9 iterations
    #pragma unroll
    for (int idx = threadIdx.x; idx < Q01N; idx += TPB)
        q01[idx] = __ldg(&x[idx / VD]) * __ldg(&x[VD + idx % VD]);
    __syncthreads();

    const int c  = blockIdx.y;
    const int t4 = blockIdx.x * TPB + threadIdx.x;      // [0, STRIDE)
    const int m  = t4 % 12;                              // i3 segment (invariant)
    const int g0 = t4 / 12;                              // [0, 3456)
    const int i2 = g0 % VD;                              // invariant: stride/12 % 48 == 0
    int t01      = g0 / VD;                              // [0,72), += 72/iter, max 2303

    // x3 float4 for this thread's phase, pre-scaled by x2[i2]
    const float c2 = __ldg(&x[2*VD + i2]);
    float4 x3 = reinterpret_cast<const float4*>(x + 3*VD)[m];
    x3.x *= c2; x3.y *= c2; x3.z *= c2; x3.w *= c2;

    const float4* Wp = reinterpret_cast<const float4*>(W) + (size_t)c * D4 + t4;

    float acc = 0.f;
#pragma unroll 4
    for (int k = 0; k < ITERS; ++k) {
        float4 w = __ldcs(Wp);           // streaming: W has zero reuse
        float  p = q01[t01];             // broadcast LDS (<=2 addrs/warp)
        acc += p * (w.x*x3.x + w.y*x3.y + w.z*x3.z + w.w*x3.w);
        Wp  += STRIDE;
        t01 += 72;
    }

    // Deterministic block reduction
    #pragma unroll
    for (int off = 16; off; off >>= 1)
        acc += __shfl_down_sync(0xFFFFFFFFu, acc, off);

    if ((threadIdx.x & 31) == 0) sred[threadIdx.x >> 5] = acc;
    __syncthreads();

    // Warp 0: publish partial, take per-class ticket; last block of this
    // class reduces its 162 partials. No fences, no extra block barriers.
    if (threadIdx.x < 32) {
        unsigned t = 0;
        if (threadIdx.x == 0) {
            float v = 0.f;
            #pragma unroll
            for (int w = 0; w < TPB/32; ++w) v += sred[w];
            __stcg(&g_part[c * GX + blockIdx.x], v);      // L2 direct
            t = atom_add_acqrel(&g_tick[c], 1u);          // release prior store
        }
        t = __shfl_sync(0xFFFFFFFFu, t, 0);
        if (t == GX - 1) {                                // last block of class c
            const int lane = threadIdx.x;
            float s = 0.f;
            for (int i = lane; i < GX; i += 32)
                s += __ldcg(&g_part[c * GX + i]);         // L2-fresh, bypass L1
            #pragma unroll
            for (int off = 16; off; off >>= 1)
                s += __shfl_down_sync(0xFFFFFFFFu, s, off);
            if (lane == 0) {
                float r = s + __ldg(&b[c]);
                out[c] = r > 0.f ? r : 0.f;
                __stcg(&g_tick[c], 0u);                   // re-arm for next replay
            }
        }
    }
}

extern "C" void kernel_launch(void* const* d_in, const int* in_sizes, int n_in,
                              void* d_out, int out_size) {
    const float* x = nullptr; const float* W = nullptr; const float* b = nullptr;
    for (int i = 0; i < n_in; ++i) {
        if      (in_sizes[i] == 4*VD)    x = (const float*)d_in[i];
        else if (in_sizes[i] == NC*DTOT) W = (const float*)d_in[i];
        else if (in_sizes[i] == NC)      b = (const float*)d_in[i];
    }

    dim3 grid(GX, NC);
    k_main<<<grid, TPB>>>(W, x, b, (float*)d_out);
}

// round 13
// speedup vs baseline: 1.0367x; 1.0367x over previous
#include <cuda_runtime.h>

#define VD 48
#define NC 16
#define G3 (VD*VD*VD)            // 110592 groups
#define DTOT (G3*VD)             // 5308416 cross-feature dims
#define D4 (DTOT/4)              // 1327104 float4 per class row
#define GX 162                   // blocks per class
#define TPB 256
#define STRIDE (GX*TPB)          // 41472 (divisible by 12)
#define ITERS (D4/STRIDE)        // 32
#define Q01N (VD*VD)             // 2304

__device__ float g_part[NC*GX];
__device__ unsigned int g_tick[NC];   // zero-init; reset by each class's last block

// Release-only GPU-scope atomic add: orders this thread's prior global stores
// into L2 before the increment becomes visible. No acquire => no L1D
// invalidate on the 2576 non-winner blocks.
__device__ __forceinline__ unsigned atom_add_release(unsigned* p, unsigned v) {
    unsigned old;
    asm volatile("atom.release.gpu.global.add.u32 %0, [%1], %2;"
                 : "=r"(old) : "l"(p), "r"(v) : "memory");
    return old;
}

// Acquire load, executed ONLY by the 16 winner blocks: orders subsequent
// partial reads after all writers' released stores.
__device__ __forceinline__ unsigned ld_acquire(const unsigned* p) {
    unsigned v;
    asm volatile("ld.acquire.gpu.global.u32 %0, [%1];"
                 : "=r"(v) : "l"(p) : "memory");
    return v;
}

// Fused: streaming GEMV over W (340 MB, read once), p012 factored as
// q01[i0*48+i1] (shared) * x2[i2] (folded into x3 regs). Per-class ticket:
// last block of each class reduces that class's 162 partials (warp 0 only).
__global__ void __launch_bounds__(TPB) k_main(const float* __restrict__ W,
                                              const float* __restrict__ x,
                                              const float* __restrict__ b,
                                              float* __restrict__ out) {
    __shared__ float q01[Q01N];          // x0 (x) x1 outer product, 9 KB
    __shared__ float sred[TPB/32];

    // Build q01 cooperatively: 2304 / 256 = 9 iterations
    #pragma unroll
    for (int idx = threadIdx.x; idx < Q01N; idx += TPB)
        q01[idx] = __ldg(&x[idx / VD]) * __ldg(&x[VD + idx % VD]);
    __syncthreads();

    const int c  = blockIdx.y;
    const int t4 = blockIdx.x * TPB + threadIdx.x;      // [0, STRIDE)
    const int m  = t4 % 12;                              // i3 segment (invariant)
    const int g0 = t4 / 12;                              // [0, 3456)
    const int i2 = g0 % VD;                              // invariant: stride/12 % 48 == 0
    int t01      = g0 / VD;                              // [0,72), += 72/iter, max 2303

    // x3 float4 for this thread's phase, pre-scaled by x2[i2]
    const float c2 = __ldg(&x[2*VD + i2]);
    float4 x3 = reinterpret_cast<const float4*>(x + 3*VD)[m];
    x3.x *= c2; x3.y *= c2; x3.z *= c2; x3.w *= c2;

    const float4* Wp = reinterpret_cast<const float4*>(W) + (size_t)c * D4 + t4;

    float acc = 0.f;
#pragma unroll 4
    for (int k = 0; k < ITERS; ++k) {
        float4 w = __ldcs(Wp);           // streaming: W has zero reuse
        float  p = q01[t01];             // broadcast LDS (<=2 addrs/warp)
        acc += p * (w.x*x3.x + w.y*x3.y + w.z*x3.z + w.w*x3.w);
        Wp  += STRIDE;
        t01 += 72;
    }

    // Deterministic block reduction
    #pragma unroll
    for (int off = 16; off; off >>= 1)
        acc += __shfl_down_sync(0xFFFFFFFFu, acc, off);

    if ((threadIdx.x & 31) == 0) sred[threadIdx.x >> 5] = acc;
    __syncthreads();

    // Warp 0: publish partial (release), take per-class ticket; last block of
    // this class acquires once, then reduces its 162 partials from L2.
    if (threadIdx.x < 32) {
        unsigned t = 0;
        if (threadIdx.x == 0) {
            float v = 0.f;
            #pragma unroll
            for (int w = 0; w < TPB/32; ++w) v += sred[w];
            __stcg(&g_part[c * GX + blockIdx.x], v);      // L2 direct
            t = atom_add_release(&g_tick[c], 1u);         // release prior store
        }
        t = __shfl_sync(0xFFFFFFFFu, t, 0);
        if (t == GX - 1) {                                // last block of class c
            if (threadIdx.x == 0) (void)ld_acquire(&g_tick[c]);  // 16 acquires total
            __syncwarp();
            const int lane = threadIdx.x;
            float s = 0.f;
            for (int i = lane; i < GX; i += 32)
                s += __ldcg(&g_part[c * GX + i]);         // L2-fresh, bypass L1
            #pragma unroll
            for (int off = 16; off; off >>= 1)
                s += __shfl_down_sync(0xFFFFFFFFu, s, off);
            if (lane == 0) {
                float r = s + __ldg(&b[c]);
                out[c] = r > 0.f ? r : 0.f;
                __stcg(&g_tick[c], 0u);                   // re-arm for next replay
            }
        }
    }
}

extern "C" void kernel_launch(void* const* d_in, const int* in_sizes, int n_in,
                              void* d_out, int out_size) {
    const float* x = nullptr; const float* W = nullptr; const float* b = nullptr;
    for (int i = 0; i < n_in; ++i) {
        if      (in_sizes[i] == 4*VD)    x = (const float*)d_in[i];
        else if (in_sizes[i] == NC*DTOT) W = (const float*)d_in[i];
        else if (in_sizes[i] == NC)      b = (const float*)d_in[i];
    }

    dim3 grid(GX, NC);
    k_main<<<grid, TPB>>>(W, x, b, (float*)d_out);
}

// round 15
// speedup vs baseline: 1.0555x; 1.0181x over previous
#include <cuda_runtime.h>

#define VD 48
#define NC 16
#define G3 (VD*VD*VD)            // 110592 groups
#define DTOT (G3*VD)             // 5308416 cross-feature dims
#define D4 (DTOT/4)              // 1327104 float4 per class row
#define GX 72                    // blocks per class -> 72*16 = 1152 blocks = ONE wave @ occ 8
#define TPB 256
#define STRIDE (GX*TPB)          // 18432 (divisible by 12)
#define ITERS (D4/STRIDE)        // 72
#define GSTRIDE (STRIDE/12)      // 1536 (divisible by 48 -> i2 loop-invariant)
#define Q01N (VD*VD)             // 2304

__device__ float g_part[NC*GX];
__device__ unsigned int g_tick[NC];   // zero-init; reset by each class's last block

// Release-only GPU-scope atomic add: orders this thread's prior global stores
// into L2 before the increment becomes visible. No acquire => no L1D
// invalidate on non-winner blocks.
__device__ __forceinline__ unsigned atom_add_release(unsigned* p, unsigned v) {
    unsigned old;
    asm volatile("atom.release.gpu.global.add.u32 %0, [%1], %2;"
                 : "=r"(old) : "l"(p), "r"(v) : "memory");
    return old;
}

// Acquire load, executed ONLY by the 16 winner blocks.
__device__ __forceinline__ unsigned ld_acquire(const unsigned* p) {
    unsigned v;
    asm volatile("ld.acquire.gpu.global.u32 %0, [%1];"
                 : "=r"(v) : "l"(p) : "memory");
    return v;
}

// Fused single-wave streaming GEMV over W (340 MB, read once). p012 factored
// as q01[i0*48+i1] (shared) * x2[i2] (folded into x3 registers). Per-class
// release-ticket: last block of each class reduces its 72 partials (warp 0).
__global__ void __launch_bounds__(TPB) k_main(const float* __restrict__ W,
                                              const float* __restrict__ x,
                                              const float* __restrict__ b,
                                              float* __restrict__ out) {
    __shared__ float q01[Q01N];          // x0 (x) x1 outer product, 9 KB
    __shared__ float sred[TPB/32];

    // Build q01 cooperatively: 2304 / 256 = 9 iterations
    #pragma unroll
    for (int idx = threadIdx.x; idx < Q01N; idx += TPB)
        q01[idx] = __ldg(&x[idx / VD]) * __ldg(&x[VD + idx % VD]);
    __syncthreads();

    const int c  = blockIdx.y;
    const int t4 = blockIdx.x * TPB + threadIdx.x;      // [0, STRIDE)
    const int m  = t4 % 12;                              // i3 segment (invariant)
    const int g0 = t4 / 12;                              // [0, 1536)
    const int i2 = g0 % VD;                              // invariant: GSTRIDE % 48 == 0
    int t01      = g0 / VD;                              // [0,32), += 32/iter, max 2303

    // x3 float4 for this thread's phase, pre-scaled by x2[i2]
    const float c2 = __ldg(&x[2*VD + i2]);
    float4 x3 = reinterpret_cast<const float4*>(x + 3*VD)[m];
    x3.x *= c2; x3.y *= c2; x3.z *= c2; x3.w *= c2;

    const float4* Wp = reinterpret_cast<const float4*>(W) + (size_t)c * D4 + t4;

    float acc = 0.f;
#pragma unroll 4
    for (int k = 0; k < ITERS; ++k) {
        float4 w = __ldcs(Wp);           // streaming: W has zero reuse
        float  p = q01[t01];             // broadcast LDS (<=2 addrs/warp)
        acc += p * (w.x*x3.x + w.y*x3.y + w.z*x3.z + w.w*x3.w);
        Wp  += STRIDE;
        t01 += 32;                        // GSTRIDE/48
    }

    // Deterministic block reduction
    #pragma unroll
    for (int off = 16; off; off >>= 1)
        acc += __shfl_down_sync(0xFFFFFFFFu, acc, off);

    if ((threadIdx.x & 31) == 0) sred[threadIdx.x >> 5] = acc;
    __syncthreads();

    // Warp 0: publish partial (release), take per-class ticket; last block of
    // this class acquires once, then reduces its 72 partials from L2.
    if (threadIdx.x < 32) {
        unsigned t = 0;
        if (threadIdx.x == 0) {
            float v = 0.f;
            #pragma unroll
            for (int w = 0; w < TPB/32; ++w) v += sred[w];
            __stcg(&g_part[c * GX + blockIdx.x], v);      // L2 direct
            t = atom_add_release(&g_tick[c], 1u);         // release prior store
        }
        t = __shfl_sync(0xFFFFFFFFu, t, 0);
        if (t == GX - 1) {                                // last block of class c
            if (threadIdx.x == 0) (void)ld_acquire(&g_tick[c]);  // 16 acquires total
            __syncwarp();
            const int lane = threadIdx.x;
            float s = 0.f;
            #pragma unroll
            for (int i = lane; i < GX; i += 32)
                s += __ldcg(&g_part[c * GX + i]);         // L2-fresh, bypass L1
            #pragma unroll
            for (int off = 16; off; off >>= 1)
                s += __shfl_down_sync(0xFFFFFFFFu, s, off);
            if (lane == 0) {
                float r = s + __ldg(&b[c]);
                out[c] = r > 0.f ? r : 0.f;
                __stcg(&g_tick[c], 0u);                   // re-arm for next replay
            }
        }
    }
}

extern "C" void kernel_launch(void* const* d_in, const int* in_sizes, int n_in,
                              void* d_out, int out_size) {
    const float* x = nullptr; const float* W = nullptr; const float* b = nullptr;
    for (int i = 0; i < n_in; ++i) {
        if      (in_sizes[i] == 4*VD)    x = (const float*)d_in[i];
        else if (in_sizes[i] == NC*DTOT) W = (const float*)d_in[i];
        else if (in_sizes[i] == NC)      b = (const float*)d_in[i];
    }

    dim3 grid(GX, NC);
    k_main<<<grid, TPB>>>(W, x, b, (float*)d_out);
}

// round 16
// speedup vs baseline: 1.0711x; 1.0148x over previous
#include <cuda_runtime.h>

#define VD 48
#define NC 16
#define G3 (VD*VD*VD)            // 110592 groups
#define DTOT (G3*VD)             // 5308416 cross-feature dims
#define D4 (DTOT/4)              // 1327104 float4 per class row
#define GX 18                    // blocks per class -> 18*16 = 288 blocks = ONE wave @ 2 CTAs/SM
#define TPB 1024                 // big CTAs: fewer CTAs/SM => less cross-CTA L1tex-queue spread
#define STRIDE (GX*TPB)          // 18432 (divisible by 12) -- identical to R15
#define ITERS (D4/STRIDE)        // 72
#define GSTRIDE (STRIDE/12)      // 1536 (divisible by 48 -> i2 loop-invariant)
#define Q01N (VD*VD)             // 2304

__device__ float g_part[NC*GX];
__device__ unsigned int g_tick[NC];   // zero-init; reset by each class's last block

// Release-only GPU-scope atomic add: orders this thread's prior global stores
// into L2 before the increment becomes visible. No acquire => no L1D
// invalidate on non-winner blocks.
__device__ __forceinline__ unsigned atom_add_release(unsigned* p, unsigned v) {
    unsigned old;
    asm volatile("atom.release.gpu.global.add.u32 %0, [%1], %2;"
                 : "=r"(old) : "l"(p), "r"(v) : "memory");
    return old;
}

// Acquire load, executed ONLY by the 16 winner blocks.
__device__ __forceinline__ unsigned ld_acquire(const unsigned* p) {
    unsigned v;
    asm volatile("ld.acquire.gpu.global.u32 %0, [%1];"
                 : "=r"(v) : "l"(p) : "memory");
    return v;
}

// Fused single-wave streaming GEMV over W (340 MB, read once). p012 factored
// as q01[i0*48+i1] (shared) * x2[i2] (folded into x3 registers). Per-class
// release-ticket: last block of each class reduces its 18 partials (warp 0).
__global__ void __launch_bounds__(TPB, 2) k_main(const float* __restrict__ W,
                                                 const float* __restrict__ x,
                                                 const float* __restrict__ b,
                                                 float* __restrict__ out) {
    __shared__ float q01[Q01N];          // x0 (x) x1 outer product, 9 KB
    __shared__ float sred[TPB/32];

    // Build q01 cooperatively: 2304 / 1024 = 2.25 iterations
    #pragma unroll
    for (int idx = threadIdx.x; idx < Q01N; idx += TPB)
        q01[idx] = __ldg(&x[idx / VD]) * __ldg(&x[VD + idx % VD]);
    __syncthreads();

    const int c  = blockIdx.y;
    const int t4 = blockIdx.x * TPB + threadIdx.x;      // [0, STRIDE)
    const int m  = t4 % 12;                              // i3 segment (invariant)
    const int g0 = t4 / 12;                              // [0, 1536)
    const int i2 = g0 % VD;                              // invariant: GSTRIDE % 48 == 0
    int t01      = g0 / VD;                              // [0,32), += 32/iter, max 2303

    // x3 float4 for this thread's phase, pre-scaled by x2[i2]
    const float c2 = __ldg(&x[2*VD + i2]);
    float4 x3 = reinterpret_cast<const float4*>(x + 3*VD)[m];
    x3.x *= c2; x3.y *= c2; x3.z *= c2; x3.w *= c2;

    const float4* Wp = reinterpret_cast<const float4*>(W) + (size_t)c * D4 + t4;

    float acc = 0.f;
#pragma unroll 4
    for (int k = 0; k < ITERS; ++k) {
        float4 w = __ldcs(Wp);           // streaming: W has zero reuse
        float  p = q01[t01];             // broadcast LDS (<=2 addrs/warp)
        acc += p * (w.x*x3.x + w.y*x3.y + w.z*x3.z + w.w*x3.w);
        Wp  += STRIDE;
        t01 += 32;                        // GSTRIDE/48
    }

    // Deterministic block reduction (32 warps)
    #pragma unroll
    for (int off = 16; off; off >>= 1)
        acc += __shfl_down_sync(0xFFFFFFFFu, acc, off);

    if ((threadIdx.x & 31) == 0) sred[threadIdx.x >> 5] = acc;
    __syncthreads();

    // Warp 0: fold 32 warp-partials, publish (release), take per-class ticket;
    // last block of this class acquires once, then reduces its 18 partials.
    if (threadIdx.x < 32) {
        float v = sred[threadIdx.x];
        #pragma unroll
        for (int off = 16; off; off >>= 1)
            v += __shfl_down_sync(0xFFFFFFFFu, v, off);

        unsigned t = 0;
        if (threadIdx.x == 0) {
            __stcg(&g_part[c * GX + blockIdx.x], v);      // L2 direct
            t = atom_add_release(&g_tick[c], 1u);         // release prior store
        }
        t = __shfl_sync(0xFFFFFFFFu, t, 0);
        if (t == GX - 1) {                                // last block of class c
            if (threadIdx.x == 0) (void)ld_acquire(&g_tick[c]);  // 16 acquires total
            __syncwarp();
            const int lane = threadIdx.x;
            float s = 0.f;
            for (int i = lane; i < GX; i += 32)
                s += __ldcg(&g_part[c * GX + i]);         // L2-fresh, bypass L1
            #pragma unroll
            for (int off = 16; off; off >>= 1)
                s += __shfl_down_sync(0xFFFFFFFFu, s, off);
            if (lane == 0) {
                float r = s + __ldg(&b[c]);
                out[c] = r > 0.f ? r : 0.f;
                __stcg(&g_tick[c], 0u);                   // re-arm for next replay
            }
        }
    }
}

extern "C" void kernel_launch(void* const* d_in, const int* in_sizes, int n_in,
                              void* d_out, int out_size) {
    const float* x = nullptr; const float* W = nullptr; const float* b = nullptr;
    for (int i = 0; i < n_in; ++i) {
        if      (in_sizes[i] == 4*VD)    x = (const float*)d_in[i];
        else if (in_sizes[i] == NC*DTOT) W = (const float*)d_in[i];
        else if (in_sizes[i] == NC)      b = (const float*)d_in[i];
    }

    dim3 grid(GX, NC);
    k_main<<<grid, TPB>>>(W, x, b, (float*)d_out);
}

// round 17
// speedup vs baseline: 1.0717x; 1.0006x over previous
#include <cuda_runtime.h>

#define VD 48
#define NC 16
#define G3 (VD*VD*VD)            // 110592 groups
#define DTOT (G3*VD)             // 5308416 cross-feature dims
#define D4 (DTOT/4)              // 1327104 float4 per class row
#define GX 18                    // blocks per class -> 288 blocks = ONE wave @ 2 CTAs/SM
#define TPB 1024
#define STRIDE (GX*TPB)          // 18432 (divisible by 12)
#define ITERS (D4/STRIDE)        // 72 (divisible by 8 for the unroll)
#define GSTRIDE (STRIDE/12)      // 1536 (divisible by 48 -> i2 loop-invariant)
#define Q01N (VD*VD)             // 2304

__device__ float g_part[NC*GX];
__device__ unsigned int g_tick[NC];   // zero-init; reset by each class's last block

// Release-only GPU-scope atomic add: orders this thread's prior global stores
// into L2 before the increment becomes visible. No acquire => no L1D
// invalidate on non-winner blocks.
__device__ __forceinline__ unsigned atom_add_release(unsigned* p, unsigned v) {
    unsigned old;
    asm volatile("atom.release.gpu.global.add.u32 %0, [%1], %2;"
                 : "=r"(old) : "l"(p), "r"(v) : "memory");
    return old;
}

// Acquire load, executed ONLY by the 16 winner blocks.
__device__ __forceinline__ unsigned ld_acquire(const unsigned* p) {
    unsigned v;
    asm volatile("ld.acquire.gpu.global.u32 %0, [%1];"
                 : "=r"(v) : "l"(p) : "memory");
    return v;
}

// Fused single-wave streaming GEMV over W (340 MB, read once). p012 factored
// as q01[i0*48+i1] (shared) * x2[i2] (folded into x3 registers). Per-class
// release-ticket: last block of each class reduces its 18 partials (warp 0).
__global__ void __launch_bounds__(TPB, 2) k_main(const float* __restrict__ W,
                                                 const float* __restrict__ x,
                                                 const float* __restrict__ b,
                                                 float* __restrict__ out) {
    __shared__ float q01[Q01N];          // x0 (x) x1 outer product, 9 KB
    __shared__ float sred[TPB/32];

    // Build q01 cooperatively
    #pragma unroll
    for (int idx = threadIdx.x; idx < Q01N; idx += TPB)
        q01[idx] = __ldg(&x[idx / VD]) * __ldg(&x[VD + idx % VD]);
    __syncthreads();

    const int c  = blockIdx.y;
    const int t4 = blockIdx.x * TPB + threadIdx.x;      // [0, STRIDE)
    const int m  = t4 % 12;                              // i3 segment (invariant)
    const int g0 = t4 / 12;                              // [0, 1536)
    const int i2 = g0 % VD;                              // invariant: GSTRIDE % 48 == 0
    int t01      = g0 / VD;                              // [0,32), += 32/iter, max 2303

    // x3 float4 for this thread's phase, pre-scaled by x2[i2]
    const float c2 = __ldg(&x[2*VD + i2]);
    float4 x3 = reinterpret_cast<const float4*>(x + 3*VD)[m];
    x3.x *= c2; x3.y *= c2; x3.z *= c2; x3.w *= c2;

    const float4* Wp = reinterpret_cast<const float4*>(W) + (size_t)c * D4 + t4;

    float acc = 0.f;
#pragma unroll 8
    for (int k = 0; k < ITERS; ++k) {
        float4 w = __ldg(Wp);            // plain cached path (read-once stream)
        float  p = q01[t01];             // broadcast LDS (<=2 addrs/warp)
        acc += p * (w.x*x3.x + w.y*x3.y + w.z*x3.z + w.w*x3.w);
        Wp  += STRIDE;
        t01 += 32;                        // GSTRIDE/48
    }

    // Deterministic block reduction (32 warps)
    #pragma unroll
    for (int off = 16; off; off >>= 1)
        acc += __shfl_down_sync(0xFFFFFFFFu, acc, off);

    if ((threadIdx.x & 31) == 0) sred[threadIdx.x >> 5] = acc;
    __syncthreads();

    // Warp 0: fold 32 warp-partials, publish (release), take per-class ticket;
    // last block of this class acquires once, then reduces its 18 partials.
    if (threadIdx.x < 32) {
        float v = sred[threadIdx.x];
        #pragma unroll
        for (int off = 16; off; off >>= 1)
            v += __shfl_down_sync(0xFFFFFFFFu, v, off);

        unsigned t = 0;
        if (threadIdx.x == 0) {
            __stcg(&g_part[c * GX + blockIdx.x], v);      // L2 direct
            t = atom_add_release(&g_tick[c], 1u);         // release prior store
        }
        t = __shfl_sync(0xFFFFFFFFu, t, 0);
        if (t == GX - 1) {                                // last block of class c
            if (threadIdx.x == 0) (void)ld_acquire(&g_tick[c]);  // 16 acquires total
            __syncwarp();
            const int lane = threadIdx.x;
            float s = 0.f;
            for (int i = lane; i < GX; i += 32)
                s += __ldcg(&g_part[c * GX + i]);         // L2-fresh, bypass L1
            #pragma unroll
            for (int off = 16; off; off >>= 1)
                s += __shfl_down_sync(0xFFFFFFFFu, s, off);
            if (lane == 0) {
                float r = s + __ldg(&b[c]);
                out[c] = r > 0.f ? r : 0.f;
                __stcg(&g_tick[c], 0u);                   // re-arm for next replay
            }
        }
    }
}

extern "C" void kernel_launch(void* const* d_in, const int* in_sizes, int n_in,
                              void* d_out, int out_size) {
    const float* x = nullptr; const float* W = nullptr; const float* b = nullptr;
    for (int i = 0; i < n_in; ++i) {
        if      (in_sizes[i] == 4*VD)    x = (const float*)d_in[i];
        else if (in_sizes[i] == NC*DTOT) W = (const float*)d_in[i];
        else if (in_sizes[i] == NC)      b = (const float*)d_in[i];
    }

    dim3 grid(GX, NC);
    k_main<<<grid, TPB>>>(W, x, b, (float*)d_out);
}